// round 15
// baseline (speedup 1.0000x reference)
#include <cuda_runtime.h>
#include <cuda_bf16.h>
#include <cstdint>
#include <math.h>

#define N_NODES 30000
#define DIM     128
#define T_LINKS 3000
#define K_NEG   75
#define NQ      (2 * T_LINKS)
#define EPSF    1e-7f
#define MAXSQ   50.0f
#define GAMMA   1.0f

#define QPB   16                      // queries per block
#define NB    (NQ / QPB)              // 375 blocks
#define TILE  64                      // candidates per smem tile (bf16)
#define NTILES 4                      // fixed screen: 256 candidates
#define NCAND (TILE * NTILES)         // 256
#define ROWW  68                      // uint32 words per bf16 row (64 data + 4 pad)
#define SCREEN_MARGIN 0.5f            // stricter screen: can only under-count

// ---------------- scratch (no device allocations allowed) ----------------
__device__ float        g_partial[NB];
__device__ unsigned int g_ticket = 0;
__device__ int          g_is64;
__device__ uint4        g_candbf[NCAND * 16];   // 256 rows x 16 uint4 (bf16x8)

static __device__ __forceinline__ unsigned int pack_bf(float a, float b) {
    __nv_bfloat162 h = __floats2bfloat162_rn(a, b);
    return *reinterpret_cast<unsigned int*>(&h);
}
static __device__ __forceinline__ __nv_bfloat162 u2b(unsigned int w) {
    return *reinterpret_cast<__nv_bfloat162*>(&w);
}
static __device__ __forceinline__ float bsum(__nv_bfloat162 a, __nv_bfloat162 b,
                                             __nv_bfloat162 c, __nv_bfloat162 d) {
    float2 f0 = __bfloat1622float2(a), f1 = __bfloat1622float2(b);
    float2 f2 = __bfloat1622float2(c), f3 = __bfloat1622float2(d);
    return ((f0.x + f0.y) + (f1.x + f1.y)) + ((f2.x + f2.y) + (f3.x + f3.y));
}

// ---------------- prep kernel: bf16 table + link dtype detection ----------------
// blocks 0..15: convert the 256 screen candidate rows fp32 -> bf16 (one uint4
// output per thread). block 16: detect links dtype (int64-LE with values <
// 30000 => all odd 32-bit words are zero).
__global__ void prep_kernel(const float* __restrict__ emb,
                            const int* __restrict__ lw) {
    if (blockIdx.x < 16) {
        const int g    = blockIdx.x * 256 + threadIdx.x;  // 0..4095
        const int cand = g >> 4;
        const int q4   = g & 15;
        const float4* E4 = (const float4*)emb;
        float4 f0 = E4[(size_t)cand * (DIM / 4) + 2 * q4];
        float4 f1 = E4[(size_t)cand * (DIM / 4) + 2 * q4 + 1];
        uint4 w;
        w.x = pack_bf(f0.x, f0.y); w.y = pack_bf(f0.z, f0.w);
        w.z = pack_bf(f1.x, f1.y); w.w = pack_bf(f1.z, f1.w);
        g_candbf[g] = w;
    } else {
        int loc = 0;
        for (int i = threadIdx.x; i < T_LINKS; i += 256)
            if (lw[2 * i + 1] != 0) loc = 1;
        const int any = __syncthreads_or(loc);
        if (threadIdx.x == 0) g_is64 = !any;
    }
}

// Exact fp32 fallback: top-75 largest (prod, -idx) lexicographic; whole warp
// calls uniformly. __noinline__ keeps the hot path's register count low.
static __device__ __noinline__ float fallback_topk(
    const float* __restrict__ emb, int qrow, float D,
    float cscale, float K, float thr_theta, int lane) {
    const float* qp = emb + (size_t)qrow * DIM;
    float prevP = INFINITY; int prevI = -1;
    float s = 0.0f;
    for (int pick = 0; pick < K_NEG; ++pick) {
        float bp = -INFINITY; int bi = 0x7fffffff;
        for (int n = lane; n < N_NODES; n += 32) {
            const float* e = emb + (size_t)n * DIM;
            float p = -qp[0] * e[0];
            #pragma unroll 8
            for (int d = 1; d < DIM; ++d) p += qp[d] * e[d];
            bool after = (p < prevP) || (p == prevP && n > prevI);
            if (after && (p > bp || (p == bp && n < bi))) { bp = p; bi = n; }
        }
        #pragma unroll
        for (int o = 16; o; o >>= 1) {
            float op = __shfl_xor_sync(0xffffffffu, bp, o);
            int   oi = __shfl_xor_sync(0xffffffffu, bi, o);
            if (op > bp || (op == bp && oi < bi)) { bp = op; bi = oi; }
        }
        prevP = bp; prevI = bi;
        float t2 = fmaxf(-bp * cscale, thr_theta);
        float a2 = acoshf(t2);
        float sq = fminf(K * a2 * a2, MAXSQ);
        s += fmaxf(D - sq, 0.0f);
    }
    return s;
}

// Math: sq(prod) = min(K*acosh(max(-prod*c,1+eps))^2, 50) is weakly monotone
// non-increasing in prod => the 75 smallest distances are the 75 largest
// Minkowski prods. With emb ~ N(0,1), ~16000/30000 candidates clip to
// theta = 1+eps (global minimum sq_min), so the 75 nearest all have
// sq == sq_min exactly and the row contribution is 75*relu(D - sq_min).
// Screen: fixed 256 candidates in bf16 with a +0.5 stricter threshold
// (hits ~133, 7σ above 75; a counted candidate is guaranteed truly clipped;
// any under-count falls to the exact fp32 fallback -> always correct).
// Layout (R12, proven): lane computes 4 dots (2 cands x 2 queries); warp
// covers 16 cands x 8 queries; candidate tiles staged bf16 from the prep
// table with cross-tile register prefetch.
__global__ void __launch_bounds__(256, 3)
fused_kernel(const float* __restrict__ emb,
             const float* __restrict__ cptr,
             const void*  __restrict__ links,
             float* __restrict__ out) {
    __shared__ __align__(16) unsigned int s_cand[TILE][ROWW];  // 17408 B
    __shared__ __align__(16) unsigned int s_q[QPB][ROWW];      //  4352 B
    __shared__ float s_D[QPB];
    __shared__ int   s_qrow[QPB];
    __shared__ int   s_qcnt[QPB];
    __shared__ float s_wsum[8];
    __shared__ float s_red[256];
    __shared__ int   s_islast;

    const int t    = threadIdx.x;
    const int wid  = t >> 5;
    const int lane = t & 31;
    const int bid  = blockIdx.x;
    const int is64 = g_is64;

    const float c  = cptr[0];
    const float K  = 1.0f / c;
    const float thr_theta = 1.0f + EPSF;     // rounds to 1+2^-23, same as jax fp32
    const float prod_thr  = -thr_theta * K;  // exact clip threshold
    const float scr_thr   = prod_thr + SCREEN_MARGIN;
    float acm = acoshf(thr_theta);
    const float sq_min = fminf(K * acm * acm, MAXSQ);

    const float4* E4 = (const float4*)emb;

    // ---- prefetch tile 0 (overlaps with query setup below) ----
    uint4 pf0 = g_candbf[t];
    uint4 pf1 = g_candbf[t + 256];
    uint4 pf2 = g_candbf[t + 512];
    uint4 pf3 = g_candbf[t + 768];

    // ---- per-warp setup: warp w owns queries 2w, 2w+1 ----
    #pragma unroll
    for (int j = 0; j < 2; ++j) {
        const int q  = 2 * wid + j;               // 0..15
        const int gq = bid * QPB + q;
        const int li   = gq % T_LINKS;
        const int side = gq / T_LINKS;
        int l, r;
        if (is64) {
            const long long* p = (const long long*)links;
            l = (int)p[2 * li]; r = (int)p[2 * li + 1];
        } else {
            const int* p = (const int*)links;
            l = p[2 * li]; r = p[2 * li + 1];
        }
        // D = sqdist(left,right) + GAMMA (fp32 exact)
        float4 lv = E4[(size_t)l * (DIM / 4) + lane];
        float4 rv = E4[(size_t)r * (DIM / 4) + lane];
        float pd = lv.x * rv.x + lv.y * rv.y + lv.z * rv.z + lv.w * rv.w;
        if (lane == 0) pd -= 2.0f * lv.x * rv.x;  // Minkowski: -x0*y0
        #pragma unroll
        for (int o = 16; o; o >>= 1) pd += __shfl_xor_sync(0xffffffffu, pd, o);
        float th = fmaxf(-pd * c, thr_theta);
        float ac = acoshf(th);
        const int qrow = (side == 0) ? l : r;
        if (lane == 0) {
            s_D[q]    = fminf(K * ac * ac, MAXSQ) + GAMMA;
            s_qrow[q] = qrow;
        }
        // stage query row as bf16 (dim0 negated: plain dot == Minkowski dot)
        float4 qv = E4[(size_t)qrow * (DIM / 4) + lane];
        if (lane == 0) qv.x = -qv.x;
        uint2 w2; w2.x = pack_bf(qv.x, qv.y); w2.y = pack_bf(qv.z, qv.w);
        *(uint2*)&s_q[q][lane * 2] = w2;
    }

    // ---- lane roles: 2 cands x 2 queries per lane ----
    const int qsel = lane & 3;               // query pair: 2*qsel, 2*qsel+1
    const int csel = lane >> 2;              // cand slots: csel, csel+8
    const int qg   = (wid >> 2) * 8;         // query group base (0 or 8)
    const int cg   = (wid & 3) * 16;         // cand group base within tile
    const unsigned int* q0r = &s_q[qg + 2 * qsel][0];
    const unsigned int* q1r = &s_q[qg + 2 * qsel + 1][0];
    const unsigned int* c0r = &s_cand[cg + csel][0];
    const unsigned int* c1r = &s_cand[cg + csel + 8][0];

    const int row = t >> 4;                  // staging row / word group
    const int q4  = t & 15;

    int cnt_q0 = 0, cnt_q1 = 0;

    // ---- fixed 4-tile screen with cross-tile register prefetch ----
    for (int tile = 0; tile < NTILES; ++tile) {
        // STS prefetched tile
        *(uint4*)&s_cand[row][q4 << 2]      = pf0;
        *(uint4*)&s_cand[row + 16][q4 << 2] = pf1;
        *(uint4*)&s_cand[row + 32][q4 << 2] = pf2;
        *(uint4*)&s_cand[row + 48][q4 << 2] = pf3;
        __syncthreads();

        // prefetch next tile while computing this one
        if (tile < NTILES - 1) {
            const int nb = (tile + 1) * 1024 + t;
            pf0 = g_candbf[nb];
            pf1 = g_candbf[nb + 256];
            pf2 = g_candbf[nb + 512];
            pf3 = g_candbf[nb + 768];
        }

        __nv_bfloat162 z = __float2bfloat162_rn(0.f);
        __nv_bfloat162 a00x = z, a00y = z, a00z = z, a00w = z;
        __nv_bfloat162 a01x = z, a01y = z, a01z = z, a01w = z;
        __nv_bfloat162 a10x = z, a10y = z, a10z = z, a10w = z;
        __nv_bfloat162 a11x = z, a11y = z, a11z = z, a11w = z;
        #pragma unroll 8
        for (int i = 0; i < 16; ++i) {
            uint4 av0 = *(const uint4*)&c0r[i << 2];
            uint4 av1 = *(const uint4*)&c1r[i << 2];
            uint4 bv0 = *(const uint4*)&q0r[i << 2];
            uint4 bv1 = *(const uint4*)&q1r[i << 2];
            a00x = __hfma2(u2b(av0.x), u2b(bv0.x), a00x);
            a00y = __hfma2(u2b(av0.y), u2b(bv0.y), a00y);
            a00z = __hfma2(u2b(av0.z), u2b(bv0.z), a00z);
            a00w = __hfma2(u2b(av0.w), u2b(bv0.w), a00w);
            a01x = __hfma2(u2b(av0.x), u2b(bv1.x), a01x);
            a01y = __hfma2(u2b(av0.y), u2b(bv1.y), a01y);
            a01z = __hfma2(u2b(av0.z), u2b(bv1.z), a01z);
            a01w = __hfma2(u2b(av0.w), u2b(bv1.w), a01w);
            a10x = __hfma2(u2b(av1.x), u2b(bv0.x), a10x);
            a10y = __hfma2(u2b(av1.y), u2b(bv0.y), a10y);
            a10z = __hfma2(u2b(av1.z), u2b(bv0.z), a10z);
            a10w = __hfma2(u2b(av1.w), u2b(bv0.w), a10w);
            a11x = __hfma2(u2b(av1.x), u2b(bv1.x), a11x);
            a11y = __hfma2(u2b(av1.y), u2b(bv1.y), a11y);
            a11z = __hfma2(u2b(av1.z), u2b(bv1.z), a11z);
            a11w = __hfma2(u2b(av1.w), u2b(bv1.w), a11w);
        }
        float d00 = bsum(a00x, a00y, a00z, a00w);
        float d01 = bsum(a01x, a01y, a01z, a01w);
        float d10 = bsum(a10x, a10y, a10z, a10w);
        float d11 = bsum(a11x, a11y, a11z, a11w);
        cnt_q0 += (d00 >= scr_thr) + (d10 >= scr_thr);
        cnt_q1 += (d01 >= scr_thr) + (d11 >= scr_thr);
        __syncthreads();                     // compute done before restage
    }

    // ---- aggregate counts: lanes with equal (lane&3) share the query pair ----
    #pragma unroll
    for (int o = 4; o <= 16; o <<= 1) {
        cnt_q0 += __shfl_xor_sync(0xffffffffu, cnt_q0, o);
        cnt_q1 += __shfl_xor_sync(0xffffffffu, cnt_q1, o);
    }
    // cross-warp combination: 4 warps share each query group, each covered
    // only its own cand group -> combine via shared atomics.
    if (t < QPB) s_qcnt[t] = 0;
    __syncthreads();
    if (lane < 4) {
        if (cnt_q0) atomicAdd(&s_qcnt[qg + 2 * lane], cnt_q0);
        if (cnt_q1) atomicAdd(&s_qcnt[qg + 2 * lane + 1], cnt_q1);
    }
    __syncthreads();

    // ---- per-warp contributions: warp w -> queries 2w, 2w+1 ----
    float contrib = 0.0f;
    #pragma unroll
    for (int j = 0; j < 2; ++j) {
        const int q = 2 * wid + j;
        const float D = s_D[q];
        if (s_qcnt[q] >= K_NEG) {
            contrib += (float)K_NEG * fmaxf(D - sq_min, 0.0f);
        } else {
            contrib += fallback_topk(emb, s_qrow[q], D, c, K, thr_theta, lane);
        }
    }

    if (lane == 0) s_wsum[wid] = contrib;
    __syncthreads();

    // ---- block sum -> partial, last-block-done final reduction ----
    if (t == 0) {
        float bs = 0.0f;
        #pragma unroll
        for (int w = 0; w < 8; ++w) bs += s_wsum[w];
        g_partial[bid] = bs;
        __threadfence();
        unsigned old = atomicInc(&g_ticket, NB - 1);  // wraps to 0 for replays
        s_islast = (old == NB - 1);
    }
    __syncthreads();

    if (s_islast) {
        float s = 0.0f;
        for (int i = t; i < NB; i += 256) s += g_partial[i];
        s_red[t] = s;
        __syncthreads();
        #pragma unroll
        for (int o = 128; o; o >>= 1) {
            if (t < o) s_red[t] += s_red[t + o];
            __syncthreads();
        }
        if (t == 0)
            out[0] = s_red[0] / (2.0f * (float)K_NEG * (float)T_LINKS);
    }
}

extern "C" void kernel_launch(void* const* d_in, const int* in_sizes, int n_in,
                              void* d_out, int out_size) {
    const float* emb   = (const float*)d_in[0];
    const float* cptr  = (const float*)d_in[1];
    const void*  links = d_in[2];

    prep_kernel<<<17, 256>>>(emb, (const int*)links);
    fused_kernel<<<NB, 256>>>(emb, cptr, links, (float*)d_out);
}